// round 10
// baseline (speedup 1.0000x reference)
#include <cuda_runtime.h>
#include <cuda_bf16.h>

// LocalPatternExtractor: binary-weight dw-conv -> binary pw-conv -> BN -> 4-step
// quantized LIF. Forward-value analysis: quantize_pot_ste clips the membrane
// potential to round(v/step) in [-128,127] with step = 1/128, so quantized mem
// is <= 127/128 < THRESHOLD = 1.0; the spike forward value is the hard
// comparison (mem >= THRESHOLD) on that quantized mem (sigmoid surrogate is
// forward-canceled by the stop_gradient STE). No spike ever fires: out == 0
// everywhere, reg_loss = 0.01 * mean(0) = 0. Kernel job: write out_size float
// zeros over the 0xAA-poisoned d_out.
//
// R4: fused tail kernel away (16.9 -> 14.8 us total, kernel 13.6 us).
// R7: persistent grid-stride, occ 26%->56%: kernel time UNCHANGED.
// R8: cudaMemsetAsync (driver fill path): total IDENTICAL (14.816 us).
//     => path-independent LTS write-port ceiling ~6.0 TB/s for 81.9 MB of
//     stores (L2-resident; DRAM only 20%). TMA shares the same LTS cap.
//     Residual ~1.2 us = graph-replay overhead, not controllable here.
// R9: last untested knob — sm_100+ 256-bit stores (st.global.v8.f32):
//     half the STG issue count, 1 KB contiguous burst per warp. Expected
//     neutral-to-marginal; if neutral, the write-port floor is confirmed
//     from both the issue side and the memory side and this kernel is final.

__global__ void __launch_bounds__(256) lpe_zero_v8(float* __restrict__ out,
                                                   long long n) {
    // Each thread covers 8 floats (32 B) with one 256-bit store.
    long long i8 = ((long long)blockIdx.x * blockDim.x + threadIdx.x) << 3;
    if (i8 + 7 < n) {
        asm volatile(
            "st.global.v8.f32 [%0], {%1,%1,%1,%1,%1,%1,%1,%1};"
            :: "l"(out + i8), "f"(0.0f) : "memory");
    } else if (i8 < n) {
        // Straddling thread: scalar tail (at most 7 elements), same node.
        for (long long j = i8; j < n; ++j) out[j] = 0.f;
    }
}

extern "C" void kernel_launch(void* const* d_in, const int* in_sizes, int n_in,
                              void* d_out, int out_size) {
    (void)d_in; (void)in_sizes; (void)n_in;

    long long n        = (long long)out_size;      // 20,480,001 floats
    long long nthreads = (n + 7) >> 3;             // one 32B store per thread
    const int threads  = 256;
    long long blocks   = (nthreads + threads - 1) / threads;

    lpe_zero_v8<<<(unsigned)blocks, threads>>>((float*)d_out, n);
}

// round 11
// speedup vs baseline: 1.0151x; 1.0151x over previous
#include <cuda_runtime.h>
#include <cuda_bf16.h>

// LocalPatternExtractor: binary-weight dw-conv -> binary pw-conv -> BN -> 4-step
// quantized LIF. Forward-value analysis: quantize_pot_ste clips the membrane
// potential to round(v/step) in [-128,127] with step = 1/128, so quantized mem
// is <= 127/128 < THRESHOLD = 1.0; the spike forward value is the hard
// comparison (mem >= THRESHOLD) on that quantized mem (sigmoid surrogate is
// forward-canceled by the stop_gradient STE). No spike ever fires: out == 0
// everywhere, reg_loss = 0.01 * mean(0) = 0. Kernel job: write out_size float
// zeros over the 0xAA-poisoned d_out.
//
// Evidence trail:
// R4: fused tail kernel away (16.9 -> 14.8 us total, kernel 13.6 us).
// R7: persistent grid-stride, occ 26%->56%: kernel time UNCHANGED (13.8).
// R8: cudaMemsetAsync driver fill path: total IDENTICAL (14.816 us).
// R9: st.global.v8.f32: kernel 13.6 -> 13.2 us (best device time); total
//     wobbled up on replay-overhead noise (1.2 -> 1.86 us gap).
// => Four independent mechanisms at 13.2-13.8 us for 81.9 MB: hard
//    path-independent LTS write-port ceiling (~6.2 TB/s; "L2=52%" = write
//    port saturated out of combined LTS peak; stores cannot bypass LTS).
// R10: keep v8 stores (best kernel time), halve CTA count with 512-thread
//      blocks to trim front-end cost; tail fused. This is the floor config.

__global__ void __launch_bounds__(512) lpe_zero_v8(float* __restrict__ out,
                                                   long long n) {
    // One 256-bit store (8 floats, 32 B) per thread; warp = 1 KB burst.
    long long i8 = ((long long)blockIdx.x * blockDim.x + threadIdx.x) << 3;
    if (i8 + 7 < n) {
        asm volatile(
            "st.global.v8.f32 [%0], {%1,%1,%1,%1,%1,%1,%1,%1};"
            :: "l"(out + i8), "f"(0.0f) : "memory");
    } else if (i8 < n) {
        // Straddling thread: scalar tail (at most 7 elements), same node.
        for (long long j = i8; j < n; ++j) out[j] = 0.f;
    }
}

extern "C" void kernel_launch(void* const* d_in, const int* in_sizes, int n_in,
                              void* d_out, int out_size) {
    (void)d_in; (void)in_sizes; (void)n_in;

    long long n        = (long long)out_size;      // 20,480,001 floats
    long long nthreads = (n + 7) >> 3;             // one 32B store per thread
    const int threads  = 512;
    long long blocks   = (nthreads + threads - 1) / threads;  // 5001

    lpe_zero_v8<<<(unsigned)blocks, threads>>>((float*)d_out, n);
}

// round 13
// speedup vs baseline: 1.0195x; 1.0043x over previous
#include <cuda_runtime.h>
#include <cuda_bf16.h>

// LocalPatternExtractor: binary-weight dw-conv -> binary pw-conv -> BN -> 4-step
// quantized LIF. Forward-value analysis: quantize_pot_ste clips the membrane
// potential to round(v/step) in [-128,127] with step = 1/128, so quantized mem
// is <= 127/128 < THRESHOLD = 1.0; the spike forward value is the hard
// comparison (mem >= THRESHOLD) on that quantized mem (sigmoid surrogate is
// forward-canceled by the stop_gradient STE). No spike ever fires: out == 0
// everywhere, reg_loss = 0.01 * mean(0) = 0. Kernel job: write out_size float
// zeros over the 0xAA-poisoned d_out.
//
// Evidence trail:
// R4:  fused tail kernel away (16.9 -> 14.8 us total, kernel 13.6 us).
// R7:  persistent grid-stride, occ 26%->56%: kernel time unchanged.
// R8:  cudaMemsetAsync driver fill: total identical => path-independent
//      LTS write-port ceiling (~6.2-6.4 TB/s for 81.9 MB, L2-resident).
// R9:  st.global.v8.f32: kernel 13.6 -> 13.2 us.
// R10: 512-thr blocks (5001 CTAs): kernel 12.74 us; total flat at 14.85.
//      Totals {14.82,14.82,15.07,14.85} vs kernels {13.6,13.8,13.2,12.7}:
//      the kernel->total gap grew 1.2 -> 2.1 us as the kernel shrank, i.e.
//      total is pinned at a ~14.8 us replay/timing-overhead floor.
// R11: final micro-tune of the one live signal (fewer CTAs -> lower device
//      time): 1024-thr blocks, 2501 CTAs, one 256-bit store per thread.
//      If this ties, the problem is closed at both floors.

__global__ void __launch_bounds__(1024) lpe_zero_v8(float* __restrict__ out,
                                                    long long n) {
    // One 256-bit store (8 floats, 32 B) per thread; warp = 1 KB burst.
    long long i8 = ((long long)blockIdx.x * blockDim.x + threadIdx.x) << 3;
    if (i8 + 7 < n) {
        asm volatile(
            "st.global.v8.f32 [%0], {%1,%1,%1,%1,%1,%1,%1,%1};"
            :: "l"(out + i8), "f"(0.0f) : "memory");
    } else if (i8 < n) {
        // Straddling thread: scalar tail (at most 7 elements), same node.
        for (long long j = i8; j < n; ++j) out[j] = 0.f;
    }
}

extern "C" void kernel_launch(void* const* d_in, const int* in_sizes, int n_in,
                              void* d_out, int out_size) {
    (void)d_in; (void)in_sizes; (void)n_in;

    long long n        = (long long)out_size;      // 20,480,001 floats
    long long nthreads = (n + 7) >> 3;             // one 32B store per thread
    const int threads  = 1024;
    long long blocks   = (nthreads + threads - 1) / threads;  // 2501

    lpe_zero_v8<<<(unsigned)blocks, threads>>>((float*)d_out, n);
}